// round 1
// baseline (speedup 1.0000x reference)
#include <cuda_runtime.h>
#include <math.h>

#define SQ   1024
#define HID  768
#define NHD  12
#define DH   64
#define NG   4
#define NLAY 4
#define NEXP 8
#define FFD  3072
#define NVOC 50257

// ---------------- scratch (device globals; no allocation) ----------------
__device__ float g_h[SQ * HID];
__device__ float g_res[SQ * HID];
__device__ float g_q[SQ * HID];
__device__ float g_k[SQ * (NG * DH)];
__device__ float g_v[SQ * (NG * DH)];
__device__ float g_h1[2 * SQ * FFD];    // 25 MB
__device__ float g_eo[2 * SQ * HID];    // 6 MB
__device__ float g_gates[SQ * 2];
__device__ int   g_texp[SQ * 2];
__device__ int   g_tlocal[SQ * 2];
__device__ int   g_tslot[SQ * 2];
__device__ int   g_cnt[NEXP];
__device__ int   g_offs[NEXP];
__device__ int   g_perm[2 * SQ];
__device__ int   g_loads[NLAY * NEXP];

// ---------------- embedding ----------------
__global__ void embed_kernel(const int* __restrict__ ids,
                             const float* __restrict__ emb,
                             const float* __restrict__ pos,
                             float* __restrict__ h) {
    int s = blockIdx.x;
    int id = ids[s];
    for (int c = threadIdx.x; c < HID; c += blockDim.x)
        h[(size_t)s * HID + c] = emb[(size_t)id * HID + c] + pos[(size_t)s * HID + c];
}

// ---------------- generic tiled GEMM: C = act(A@B + bias) ----------------
// A: [M,K] (row-major, lda), B: [K,N] row-major (ldb=N), C: [M,N] (ldc)
// EXPERT: per-blockIdx.z expert; rows live in slot range [offs[e], offs[e]+cnts[e])
// GATHER: A row index comes through perm[]
template<bool GELU, bool EXPERT, bool GATHER>
__global__ __launch_bounds__(256) void gemm_t(
    const float* __restrict__ A, const float* __restrict__ B,
    const float* __restrict__ bias, float* __restrict__ C,
    int M, int N, int K, int lda, int ldc,
    const int* __restrict__ perm, const int* __restrict__ offs,
    const int* __restrict__ cnts, size_t strideB, size_t strideBias)
{
    int mcount = M, base = 0;
    if (EXPERT) {
        int e = blockIdx.z;
        mcount = cnts[e];
        base   = offs[e];
        B     += (size_t)e * strideB;
        bias  += (size_t)e * strideBias;
    }
    int m0 = blockIdx.y * 64;
    if (m0 >= mcount) return;
    int n0 = blockIdx.x * 64;

    __shared__ float As[16][68];
    __shared__ float Bs[16][64];

    int tid  = threadIdx.x;
    int aRow = tid >> 2, aK = (tid & 3) << 2;
    int bK   = tid >> 4, bCol = (tid & 15) << 2;
    int row0 = (tid >> 4) << 2, col0 = (tid & 15) << 2;

    int r = m0 + aRow;
    bool arow_ok = (r < mcount);
    size_t aoff = 0;
    if (arow_ok) {
        int phys = GATHER ? perm[base + r] : (EXPERT ? base + r : r);
        aoff = (size_t)phys * (size_t)lda;
    }
    int ncol = n0 + bCol;
    bool nvec = ((N & 3) == 0) && (ncol + 3 < N);

    float acc[4][4] = {};

    for (int k0 = 0; k0 < K; k0 += 16) {
        float4 av = make_float4(0.f, 0.f, 0.f, 0.f);
        if (arow_ok) av = *(const float4*)(A + aoff + k0 + aK);
        As[aK + 0][aRow] = av.x; As[aK + 1][aRow] = av.y;
        As[aK + 2][aRow] = av.z; As[aK + 3][aRow] = av.w;

        const float* bp = B + (size_t)(k0 + bK) * (size_t)N + ncol;
        float4 bv;
        if (nvec) bv = *(const float4*)bp;
        else {
            bv = make_float4(0.f, 0.f, 0.f, 0.f);
            if (ncol     < N) bv.x = bp[0];
            if (ncol + 1 < N) bv.y = bp[1];
            if (ncol + 2 < N) bv.z = bp[2];
            if (ncol + 3 < N) bv.w = bp[3];
        }
        *(float4*)&Bs[bK][bCol] = bv;
        __syncthreads();
#pragma unroll
        for (int kk = 0; kk < 16; kk++) {
            float4 a = *(const float4*)&As[kk][row0];
            float4 b = *(const float4*)&Bs[kk][col0];
            acc[0][0] += a.x * b.x; acc[0][1] += a.x * b.y; acc[0][2] += a.x * b.z; acc[0][3] += a.x * b.w;
            acc[1][0] += a.y * b.x; acc[1][1] += a.y * b.y; acc[1][2] += a.y * b.z; acc[1][3] += a.y * b.w;
            acc[2][0] += a.z * b.x; acc[2][1] += a.z * b.y; acc[2][2] += a.z * b.z; acc[2][3] += a.z * b.w;
            acc[3][0] += a.w * b.x; acc[3][1] += a.w * b.y; acc[3][2] += a.w * b.z; acc[3][3] += a.w * b.w;
        }
        __syncthreads();
    }

#pragma unroll
    for (int i = 0; i < 4; i++) {
        int rrel = m0 + row0 + i;
        if (rrel >= mcount) continue;
        size_t crow = (size_t)(EXPERT ? base + rrel : rrel) * (size_t)ldc;
#pragma unroll
        for (int j = 0; j < 4; j++) {
            int n = n0 + col0 + j;
            if (n >= N) continue;
            float vsum = acc[i][j] + bias[n];
            if (GELU) vsum = 0.5f * vsum * (1.f + erff(vsum * 0.70710678118654752f));
            C[crow + n] = vsum;
        }
    }
}

// ---------------- flash-style GQA attention ----------------
// grid (16 q-tiles, 12 heads), 256 threads; 64 q-rows x chunks of 32 keys
__global__ __launch_bounds__(256) void attn_kernel(
    const float* __restrict__ q, const float* __restrict__ k,
    const float* __restrict__ v, const int* __restrict__ amask,
    float* __restrict__ ao)
{
    const float SCALE = 0.125f;  // 1/sqrt(64)
    int head = blockIdx.y;
    int g    = head / (NHD / NG);   // head/3
    int q0   = blockIdx.x * 64;

    __shared__ float QsT[64][68];   // [d][row]
    __shared__ float KsT[64][33];   // [d][key]
    __shared__ float Vs [32][68];   // [key][d]
    __shared__ float PsT[32][68];   // [key][row]
    __shared__ float Mk [32];

    int tid = threadIdx.x;
    // load Q tile transposed
#pragma unroll
    for (int i = 0; i < 4; i++) {
        int idx = tid + i * 256;
        int r = idx >> 4;
        int dseg = (idx & 15) * 4;
        float4 qv = *(const float4*)(q + (size_t)(q0 + r) * HID + head * 64 + dseg);
        QsT[dseg + 0][r] = qv.x; QsT[dseg + 1][r] = qv.y;
        QsT[dseg + 2][r] = qv.z; QsT[dseg + 3][r] = qv.w;
    }

    int rg = tid >> 4;       // 0..15: row group of 4 rows
    int kg = tid & 15;       // 0..15: key pair / dim quad
    int r0 = rg * 4;
    int d0 = kg * 4;
    int j0 = kg * 2;

    float acc[4][4] = {};
    float m[4], l[4];
#pragma unroll
    for (int i = 0; i < 4; i++) { m[i] = -3.0e38f; l[i] = 0.f; }

    for (int kc = 0; kc < 32; kc++) {
        int kbase = kc * 32;
#pragma unroll
        for (int i = 0; i < 2; i++) {
            int idx = tid + i * 256;
            int kk = idx >> 4;
            int dseg = (idx & 15) * 4;
            float4 kv = *(const float4*)(k + (size_t)(kbase + kk) * (NG * DH) + g * 64 + dseg);
            KsT[dseg + 0][kk] = kv.x; KsT[dseg + 1][kk] = kv.y;
            KsT[dseg + 2][kk] = kv.z; KsT[dseg + 3][kk] = kv.w;
            float4 vv = *(const float4*)(v + (size_t)(kbase + kk) * (NG * DH) + g * 64 + dseg);
            *(float4*)&Vs[kk][dseg] = vv;
        }
        if (tid < 32) Mk[tid] = (amask[kbase + tid] == 0) ? -3.0e38f : 0.f;
        __syncthreads();

        // scores: 4 rows x 2 keys per thread
        float s0[4] = {}, s1[4] = {};
#pragma unroll
        for (int d = 0; d < 64; d++) {
            float4 a = *(const float4*)&QsT[d][r0];
            float b0 = KsT[d][j0], b1 = KsT[d][j0 + 1];
            s0[0] += a.x * b0; s1[0] += a.x * b1;
            s0[1] += a.y * b0; s1[1] += a.y * b1;
            s0[2] += a.z * b0; s1[2] += a.z * b1;
            s0[3] += a.w * b0; s1[3] += a.w * b1;
        }
        float mk0 = Mk[j0], mk1 = Mk[j0 + 1];
        float cm[4];
#pragma unroll
        for (int i = 0; i < 4; i++) {
            s0[i] = s0[i] * SCALE + mk0;
            s1[i] = s1[i] * SCALE + mk1;
            cm[i] = fmaxf(s0[i], s1[i]);
        }
#pragma unroll
        for (int o = 1; o < 16; o <<= 1)
#pragma unroll
            for (int i = 0; i < 4; i++)
                cm[i] = fmaxf(cm[i], __shfl_xor_sync(0xffffffffu, cm[i], o));

        float p0[4], p1[4], csum[4];
#pragma unroll
        for (int i = 0; i < 4; i++) {
            float nm = fmaxf(m[i], cm[i]);
            float alpha = expf(m[i] - nm);
            m[i] = nm;
            p0[i] = expf(s0[i] - nm);
            p1[i] = expf(s1[i] - nm);
            csum[i] = p0[i] + p1[i];
            l[i] *= alpha;
#pragma unroll
            for (int j = 0; j < 4; j++) acc[i][j] *= alpha;
        }
#pragma unroll
        for (int o = 1; o < 16; o <<= 1)
#pragma unroll
            for (int i = 0; i < 4; i++)
                csum[i] += __shfl_xor_sync(0xffffffffu, csum[i], o);
#pragma unroll
        for (int i = 0; i < 4; i++) l[i] += csum[i];

#pragma unroll
        for (int i = 0; i < 4; i++) {
            PsT[j0][r0 + i]     = p0[i];
            PsT[j0 + 1][r0 + i] = p1[i];
        }
        __syncthreads();

#pragma unroll
        for (int key = 0; key < 32; key++) {
            float4 pv = *(const float4*)&PsT[key][r0];
            float4 vv = *(const float4*)&Vs[key][d0];
            acc[0][0] += pv.x * vv.x; acc[0][1] += pv.x * vv.y; acc[0][2] += pv.x * vv.z; acc[0][3] += pv.x * vv.w;
            acc[1][0] += pv.y * vv.x; acc[1][1] += pv.y * vv.y; acc[1][2] += pv.y * vv.z; acc[1][3] += pv.y * vv.w;
            acc[2][0] += pv.z * vv.x; acc[2][1] += pv.z * vv.y; acc[2][2] += pv.z * vv.z; acc[2][3] += pv.z * vv.w;
            acc[3][0] += pv.w * vv.x; acc[3][1] += pv.w * vv.y; acc[3][2] += pv.w * vv.z; acc[3][3] += pv.w * vv.w;
        }
        __syncthreads();
    }

#pragma unroll
    for (int i = 0; i < 4; i++) {
        float inv = 1.f / l[i];
        float4 o;
        o.x = acc[i][0] * inv; o.y = acc[i][1] * inv;
        o.z = acc[i][2] * inv; o.w = acc[i][3] * inv;
        *(float4*)(ao + (size_t)(q0 + r0 + i) * HID + head * 64 + d0) = o;
    }
}

// ---------------- layernorm: h = LN(h + res) ----------------
__global__ __launch_bounds__(256) void ln_kernel(float* __restrict__ h,
                                                 const float* __restrict__ res,
                                                 const float* __restrict__ gam,
                                                 const float* __restrict__ bet) {
    int row = blockIdx.x;
    __shared__ float xbuf[HID];
    __shared__ float red[256];
    int tid = threadIdx.x;
    float lsum = 0.f;
    for (int c = tid; c < HID; c += 256) {
        float v = h[(size_t)row * HID + c] + res[(size_t)row * HID + c];
        xbuf[c] = v;
        lsum += v;
    }
    red[tid] = lsum; __syncthreads();
    for (int s = 128; s > 0; s >>= 1) { if (tid < s) red[tid] += red[tid + s]; __syncthreads(); }
    float mean = red[0] / (float)HID;
    __syncthreads();
    float lvar = 0.f;
    for (int c = tid; c < HID; c += 256) { float d = xbuf[c] - mean; lvar += d * d; }
    red[tid] = lvar; __syncthreads();
    for (int s = 128; s > 0; s >>= 1) { if (tid < s) red[tid] += red[tid + s]; __syncthreads(); }
    float rstd = rsqrtf(red[0] / (float)HID + 1e-5f);
    for (int c = tid; c < HID; c += 256)
        h[(size_t)row * HID + c] = (xbuf[c] - mean) * rstd * gam[c] + bet[c];
}

// ---------------- router: top-2 gating ----------------
__global__ __launch_bounds__(256) void router_kernel(
    const float* __restrict__ h, const float* __restrict__ rw,
    const float* __restrict__ rb, float* __restrict__ gates,
    int* __restrict__ texp, int* __restrict__ tlocal, int* __restrict__ cnt)
{
    int t = blockIdx.x;
    int tid = threadIdx.x;
    int e = tid >> 5, lane = tid & 31;
    float sum = 0.f;
    for (int i = lane; i < HID; i += 32)
        sum += h[(size_t)t * HID + i] * rw[i * NEXP + e];
#pragma unroll
    for (int o = 16; o > 0; o >>= 1) sum += __shfl_down_sync(0xffffffffu, sum, o);
    __shared__ float logits[NEXP];
    if (lane == 0) logits[e] = sum + rb[e];
    __syncthreads();
    if (tid == 0) {
        float mx = logits[0];
        for (int i = 1; i < NEXP; i++) mx = fmaxf(mx, logits[i]);
        float ex[NEXP], ssum = 0.f;
        for (int i = 0; i < NEXP; i++) { ex[i] = expf(logits[i] - mx); ssum += ex[i]; }
        float p[NEXP];
        for (int i = 0; i < NEXP; i++) p[i] = ex[i] / ssum;
        int i0 = 0;
        for (int i = 1; i < NEXP; i++) if (p[i] > p[i0]) i0 = i;
        int i1 = (i0 == 0) ? 1 : 0;
        for (int i = 0; i < NEXP; i++) if (i != i0 && p[i] > p[i1]) i1 = i;
        float b = expf(p[i1] - p[i0]);
        float g0 = 1.f / (1.f + b);
        float g1 = b / (1.f + b);
        gates[t * 2] = g0; gates[t * 2 + 1] = g1;
        texp[t * 2] = i0; texp[t * 2 + 1] = i1;
        tlocal[t * 2]     = atomicAdd(&cnt[i0], 1);
        tlocal[t * 2 + 1] = atomicAdd(&cnt[i1], 1);
    }
}

__global__ void zero_cnt_kernel(int* c) { if (threadIdx.x < NEXP) c[threadIdx.x] = 0; }

__global__ __launch_bounds__(256) void assign_kernel(
    const int* __restrict__ cnt, int* __restrict__ offs, int* __restrict__ perm,
    const int* __restrict__ texp, const int* __restrict__ tlocal,
    int* __restrict__ tslot, int* __restrict__ loads)
{
    __shared__ int so[NEXP];
    if (threadIdx.x == 0) {
        int acc = 0;
        for (int e = 0; e < NEXP; e++) {
            so[e] = acc; offs[e] = acc; loads[e] = cnt[e]; acc += cnt[e];
        }
    }
    __syncthreads();
    for (int i = threadIdx.x; i < 2 * SQ; i += blockDim.x) {
        int t = i >> 1;
        int slot = so[texp[i]] + tlocal[i];
        perm[slot] = t;
        tslot[i] = slot;
    }
}

__global__ __launch_bounds__(256) void combine_kernel(
    const float* __restrict__ eo, const float* __restrict__ gates,
    const int* __restrict__ tslot, float* __restrict__ res)
{
    int t = blockIdx.x;
    int s0 = tslot[t * 2], s1 = tslot[t * 2 + 1];
    float g0 = gates[t * 2], g1 = gates[t * 2 + 1];
    for (int c = threadIdx.x; c < HID; c += 256)
        res[(size_t)t * HID + c] = g0 * eo[(size_t)s0 * HID + c] + g1 * eo[(size_t)s1 * HID + c];
}

__global__ void loss_kernel(const int* __restrict__ loads, float* __restrict__ out) {
    int l = threadIdx.x;
    if (l < NLAY) {
        float mean = (float)(2 * SQ) / (float)NEXP;   // 256
        float var = 0.f;
        for (int e = 0; e < NEXP; e++) {
            float d = (float)loads[l * NEXP + e] - mean;
            var += d * d;
        }
        var /= (float)(NEXP - 1);
        out[l] = var / (mean * mean);
    }
}

// ---------------- host launch ----------------
static void launch_gemm(const float* A, const float* B, const float* bias,
                        float* C, int M, int N, int K) {
    dim3 grid((N + 63) / 64, (M + 63) / 64);
    gemm_t<false, false, false><<<grid, 256>>>(A, B, bias, C, M, N, K, K, N,
                                               nullptr, nullptr, nullptr, 0, 0);
}

extern "C" void kernel_launch(void* const* d_in, const int* in_sizes, int n_in,
                              void* d_out, int out_size) {
    const int*   ids   = (const int*)d_in[0];
    const int*   amask = (const int*)d_in[1];
    const float* emb   = (const float*)d_in[2];
    const float* pos   = (const float*)d_in[3];
    const float* qw    = (const float*)d_in[4];
    const float* qb    = (const float*)d_in[5];
    const float* kw    = (const float*)d_in[6];
    const float* kb    = (const float*)d_in[7];
    const float* vw    = (const float*)d_in[8];
    const float* vb    = (const float*)d_in[9];
    const float* rw    = (const float*)d_in[10];
    const float* rb    = (const float*)d_in[11];
    const float* fc1w  = (const float*)d_in[12];
    const float* fc1b  = (const float*)d_in[13];
    const float* fc2w  = (const float*)d_in[14];
    const float* fc2b  = (const float*)d_in[15];
    const float* lng   = (const float*)d_in[16];
    const float* lnb   = (const float*)d_in[17];
    const float* ow    = (const float*)d_in[18];
    const float* ob    = (const float*)d_in[19];
    float* out = (float*)d_out;

    float *h, *res, *qbuf, *kbuf, *vbuf, *h1, *eo, *gates;
    int *texp, *tlocal, *tslot, *cnt, *offs, *perm, *loads;
    cudaGetSymbolAddress((void**)&h, g_h);
    cudaGetSymbolAddress((void**)&res, g_res);
    cudaGetSymbolAddress((void**)&qbuf, g_q);
    cudaGetSymbolAddress((void**)&kbuf, g_k);
    cudaGetSymbolAddress((void**)&vbuf, g_v);
    cudaGetSymbolAddress((void**)&h1, g_h1);
    cudaGetSymbolAddress((void**)&eo, g_eo);
    cudaGetSymbolAddress((void**)&gates, g_gates);
    cudaGetSymbolAddress((void**)&texp, g_texp);
    cudaGetSymbolAddress((void**)&tlocal, g_tlocal);
    cudaGetSymbolAddress((void**)&tslot, g_tslot);
    cudaGetSymbolAddress((void**)&cnt, g_cnt);
    cudaGetSymbolAddress((void**)&offs, g_offs);
    cudaGetSymbolAddress((void**)&perm, g_perm);
    cudaGetSymbolAddress((void**)&loads, g_loads);

    embed_kernel<<<SQ, 256>>>(ids, emb, pos, h);

    for (int l = 0; l < NLAY; l++) {
        const float* qw_l = qw + (size_t)l * HID * HID;
        const float* qb_l = qb + (size_t)l * HID;
        const float* kw_l = kw + (size_t)l * HID * (NG * DH);
        const float* kb_l = kb + (size_t)l * (NG * DH);
        const float* vw_l = vw + (size_t)l * HID * (NG * DH);
        const float* vb_l = vb + (size_t)l * (NG * DH);
        const float* rw_l = rw + (size_t)l * HID * NEXP;
        const float* rb_l = rb + (size_t)l * NEXP;
        const float* fc1w_l = fc1w + (size_t)l * NEXP * HID * FFD;
        const float* fc1b_l = fc1b + (size_t)l * NEXP * FFD;
        const float* fc2w_l = fc2w + (size_t)l * NEXP * FFD * HID;
        const float* fc2b_l = fc2b + (size_t)l * NEXP * HID;

        launch_gemm(h, qw_l, qb_l, qbuf, SQ, HID, HID);
        launch_gemm(h, kw_l, kb_l, kbuf, SQ, NG * DH, HID);
        launch_gemm(h, vw_l, vb_l, vbuf, SQ, NG * DH, HID);

        attn_kernel<<<dim3(SQ / 64, NHD), 256>>>(qbuf, kbuf, vbuf, amask, res);
        ln_kernel<<<SQ, 256>>>(h, res, lng, lnb);

        zero_cnt_kernel<<<1, 32>>>(cnt);
        router_kernel<<<SQ, 256>>>(h, rw_l, rb_l, gates, texp, tlocal, cnt);
        assign_kernel<<<1, 256>>>(cnt, offs, perm, texp, tlocal, tslot, loads + l * NEXP);

        {   // fc1 + gelu (gathered rows)
            dim3 grid(FFD / 64, SQ / 64, NEXP);
            gemm_t<true, true, true><<<grid, 256>>>(
                h, fc1w_l, fc1b_l, h1, SQ, FFD, HID, HID, FFD,
                perm, offs, cnt, (size_t)HID * FFD, (size_t)FFD);
        }
        {   // fc2 (contiguous slots)
            dim3 grid(HID / 64, SQ / 64, NEXP);
            gemm_t<false, true, false><<<grid, 256>>>(
                h1, fc2w_l, fc2b_l, eo, SQ, HID, FFD, FFD, HID,
                nullptr, offs, cnt, (size_t)FFD * HID, (size_t)HID);
        }
        combine_kernel<<<SQ, 256>>>(eo, gates, tslot, res);
        ln_kernel<<<SQ, 256>>>(h, res, lng, lnb);
    }

    launch_gemm(h, ow, ob, out, SQ, NVOC, HID);
    loss_kernel<<<1, 32>>>(loads, out + ((size_t)out_size - NLAY));
}